// round 13
// baseline (speedup 1.0000x reference)
#include <cuda_runtime.h>
#include <cuda_bf16.h>
#include <math.h>
#include <stdint.h>

#define D_MODEL   1024
#define NUM_HEADS 16
#define D_K       64
#define SEQ       2048
#define BATCH     2
#define M_TOK     (BATCH*SEQ)   // 4096

// ---------------- scratch (no allocation allowed) ----------------
__device__ __nv_bfloat16 g_xhi[(size_t)M_TOK * D_MODEL];
__device__ __nv_bfloat16 g_xlo[(size_t)M_TOK * D_MODEL];
__device__ __nv_bfloat16 g_whi[4][(size_t)D_MODEL * D_MODEL];
__device__ __nv_bfloat16 g_wlo[4][(size_t)D_MODEL * D_MODEL];
__device__ __nv_bfloat16 g_ahi[(size_t)M_TOK * D_MODEL];            // attn out hi
__device__ __nv_bfloat16 g_alo[(size_t)M_TOK * D_MODEL];            // attn out lo

#define HSZ ((size_t)BATCH * NUM_HEADS * SEQ * D_K)
__device__ __nv_bfloat16 g_qhi[HSZ], g_qlo[HSZ];
__device__ __nv_bfloat16 g_khi[HSZ], g_klo[HSZ];
__device__ __nv_bfloat16 g_vhi[HSZ], g_vlo[HSZ];

// ---------------- helpers ----------------
__device__ __forceinline__ uint32_t smem_u32(const void* p) {
    uint32_t a;
    asm("{ .reg .u64 t; cvta.to.shared.u64 t, %1; cvt.u32.u64 %0, t; }" : "=r"(a) : "l"(p));
    return a;
}

__device__ __forceinline__ void cp_async16(uint32_t dst, const void* src) {
    asm volatile("cp.async.cg.shared.global [%0], [%1], 16;" :: "r"(dst), "l"(src));
}
#define CP_COMMIT() asm volatile("cp.async.commit_group;" ::: "memory")
#define CP_WAIT(n)  asm volatile("cp.async.wait_group %0;" :: "n"(n) : "memory")

__device__ __forceinline__ void ldmx4(uint32_t* r, uint32_t addr) {
    asm volatile("ldmatrix.sync.aligned.m8n8.x4.shared.b16 {%0,%1,%2,%3}, [%4];"
                 : "=r"(r[0]), "=r"(r[1]), "=r"(r[2]), "=r"(r[3]) : "r"(addr));
}

__device__ __forceinline__ void ldmx4t(uint32_t* r, uint32_t addr) {
    asm volatile("ldmatrix.sync.aligned.m8n8.x4.trans.shared.b16 {%0,%1,%2,%3}, [%4];"
                 : "=r"(r[0]), "=r"(r[1]), "=r"(r[2]), "=r"(r[3]) : "r"(addr));
}

__device__ __forceinline__ void mma_bf16(float* d, const uint32_t* a, const uint32_t* b) {
    asm volatile("mma.sync.aligned.m16n8k16.row.col.f32.bf16.bf16.f32 "
                 "{%0,%1,%2,%3}, {%4,%5,%6,%7}, {%8,%9}, {%0,%1,%2,%3};"
                 : "+f"(d[0]), "+f"(d[1]), "+f"(d[2]), "+f"(d[3])
                 : "r"(a[0]), "r"(a[1]), "r"(a[2]), "r"(a[3]), "r"(b[0]), "r"(b[1]));
}

__device__ __forceinline__ void split2(float a, float b, uint32_t& hi, uint32_t& lo) {
    __nv_bfloat162 h = __floats2bfloat162_rn(a, b);
    float ra = a - __bfloat162float(h.x);
    float rb = b - __bfloat162float(h.y);
    __nv_bfloat162 l = __floats2bfloat162_rn(ra, rb);
    hi = *(uint32_t*)&h;
    lo = *(uint32_t*)&l;
}

// ---------------- split conversions ----------------
__global__ void cvt_split_kernel(const float4* __restrict__ src,
                                 __nv_bfloat16* __restrict__ hi,
                                 __nv_bfloat16* __restrict__ lo, int n4)
{
    int i = blockIdx.x * blockDim.x + threadIdx.x;
    if (i >= n4) return;
    float4 v = src[i];
    __nv_bfloat16 h[4], l[4];
    float f[4] = {v.x, v.y, v.z, v.w};
#pragma unroll
    for (int j = 0; j < 4; j++) {
        h[j] = __float2bfloat16(f[j]);
        l[j] = __float2bfloat16(f[j] - __bfloat162float(h[j]));
    }
    *(uint2*)&hi[(size_t)i * 4] = *(uint2*)h;
    *(uint2*)&lo[(size_t)i * 4] = *(uint2*)l;
}

__global__ void cvt_w4_kernel(const float4* __restrict__ w0, const float4* __restrict__ w1,
                              const float4* __restrict__ w2, const float4* __restrict__ w3,
                              int n4)
{
    int i = blockIdx.x * blockDim.x + threadIdx.x;
    if (i >= n4) return;
    const int z = blockIdx.z;
    const float4* src = (z == 0) ? w0 : (z == 1) ? w1 : (z == 2) ? w2 : w3;
    float4 v = src[i];
    __nv_bfloat16 h[4], l[4];
    float f[4] = {v.x, v.y, v.z, v.w};
#pragma unroll
    for (int j = 0; j < 4; j++) {
        h[j] = __float2bfloat16(f[j]);
        l[j] = __float2bfloat16(f[j] - __bfloat162float(h[j]));
    }
    size_t base = (size_t)z * D_MODEL * D_MODEL + (size_t)i * 4;
    *(uint2*)&g_whi[0][base] = *(uint2*)h;
    *(uint2*)&g_wlo[0][base] = *(uint2*)l;
}

// ---------------- HMMA GEMM: 128(M)x256(N) tile, BK=64, 2-stage pipeline ------------
// Per stage: Ahi/Alo 128x64 (16KB each) + Whi/Wlo 256x64 (32KB each) = 96KB.
// 2 stages = 192KB smem, 1 CTA/SM, 8 warps as 2(M)x4(N), warp tile 64x64.
#define GSTAGE    98304
#define GEMM_SMEM (2 * GSTAGE)

__device__ __forceinline__ void gemm_fill256(uint32_t stg,
                                             const __nv_bfloat16* __restrict__ Ahi,
                                             const __nv_bfloat16* __restrict__ Alo,
                                             const __nv_bfloat16* __restrict__ Whi,
                                             const __nv_bfloat16* __restrict__ Wlo,
                                             int k0, int tid)
{
    const int K = D_MODEL;
#pragma unroll
    for (int i = tid; i < 1024; i += 256) {
        int row = i >> 3, slot = i & 7;
        uint32_t sw = row * 128 + ((slot ^ (row & 7)) << 4);
        cp_async16(stg + sw,         Ahi + (size_t)row * K + k0 + slot * 8);
        cp_async16(stg + 16384 + sw, Alo + (size_t)row * K + k0 + slot * 8);
    }
#pragma unroll
    for (int i = tid; i < 2048; i += 256) {
        int row = i >> 3, slot = i & 7;
        uint32_t sw = row * 128 + ((slot ^ (row & 7)) << 4);
        cp_async16(stg + 32768 + sw, Whi + (size_t)row * K + k0 + slot * 8);
        cp_async16(stg + 65536 + sw, Wlo + (size_t)row * K + k0 + slot * 8);
    }
}

__device__ __forceinline__ void mma_mainloop256(const __nv_bfloat16* __restrict__ Ahi,
                                                const __nv_bfloat16* __restrict__ Alo,
                                                const __nv_bfloat16* __restrict__ Whi,
                                                const __nv_bfloat16* __restrict__ Wlo,
                                                float acc[4][8][4],
                                                uint32_t sb, int bm, int bn,
                                                int tid, int wm, int wn, int lane)
{
    const __nv_bfloat16* A0 = Ahi + (size_t)bm * D_MODEL;
    const __nv_bfloat16* A1 = Alo + (size_t)bm * D_MODEL;
    const __nv_bfloat16* W0 = Whi + (size_t)bn * D_MODEL;
    const __nv_bfloat16* W1 = Wlo + (size_t)bn * D_MODEL;

#pragma unroll
    for (int i = 0; i < 4; i++)
#pragma unroll
        for (int j = 0; j < 8; j++)
#pragma unroll
            for (int e = 0; e < 4; e++) acc[i][j][e] = 0.f;

    const int rA = (lane & 7) + ((lane >> 3) & 1) * 8;
    const int pA = (lane >> 4) & 1;

    gemm_fill256(sb, A0, A1, W0, W1, 0, tid);
    CP_COMMIT();

    for (int c = 0; c < 16; ++c) {
        const uint32_t stg = sb + (uint32_t)(c & 1) * GSTAGE;
        const bool pf = (c + 1 < 16);
        if (pf) {
            gemm_fill256(sb + (uint32_t)((c + 1) & 1) * GSTAGE, A0, A1, W0, W1,
                         (c + 1) * 64, tid);
            CP_COMMIT();
        }
        if (pf) { CP_WAIT(1); } else { CP_WAIT(0); }
        __syncthreads();

#pragma unroll
        for (int kk = 0; kk < 4; kk++) {
            const int slot = kk * 2 + pA;
            uint32_t ah[4][4], al[4][4], bh[8][2], bl[8][2];
#pragma unroll
            for (int im = 0; im < 4; im++) {
                int row = wm + im * 16 + rA;
                uint32_t ad = stg + row * 128 + ((slot ^ (row & 7)) << 4);
                ldmx4(ah[im], ad);
                ldmx4(al[im], ad + 16384);
            }
#pragma unroll
            for (int g = 0; g < 4; g++) {
                int row = wn + g * 16 + rA;
                uint32_t bd = stg + 32768 + row * 128 + ((slot ^ (row & 7)) << 4);
                uint32_t t0[4], t1[4];
                ldmx4(t0, bd);
                ldmx4(t1, bd + 32768);
                bh[g * 2 + 0][0] = t0[0]; bh[g * 2 + 0][1] = t0[2];
                bh[g * 2 + 1][0] = t0[1]; bh[g * 2 + 1][1] = t0[3];
                bl[g * 2 + 0][0] = t1[0]; bl[g * 2 + 0][1] = t1[2];
                bl[g * 2 + 1][0] = t1[1]; bl[g * 2 + 1][1] = t1[3];
            }
#pragma unroll
            for (int im = 0; im < 4; im++)
#pragma unroll
                for (int jn = 0; jn < 8; jn++) {
                    mma_bf16(acc[im][jn], ah[im], bh[jn]);
                    mma_bf16(acc[im][jn], ah[im], bl[jn]);
                    mma_bf16(acc[im][jn], al[im], bh[jn]);
                }
        }
        __syncthreads();
    }
}

// QKV projection with fused RoPE + bf16-split epilogue (z: 0=Q,1=K,2=V).
__global__ void __launch_bounds__(256, 1) qkv_mma_kernel(const int* __restrict__ pos)
{
    extern __shared__ char smem[];
    const uint32_t sb = smem_u32(smem);
    const int z = blockIdx.z;
    const int bm = blockIdx.y * 128;
    const int bn = blockIdx.x * 256;
    const int tid  = threadIdx.x;
    const int wid  = tid >> 5;
    const int lane = tid & 31;
    const int wm = (wid >> 2) * 64;
    const int wn = (wid & 3) * 64;

    float acc[4][8][4];
    mma_mainloop256(g_xhi, g_xlo, &g_whi[z][0], &g_wlo[z][0], acc,
                    sb, bm, bn, tid, wm, wn, lane);

    const int r0 = bm + wm + (lane >> 2);
    const int c0 = bn + wn + (lane & 3) * 2;
    const int hh = (bn + wn) >> 6;      // warp's 64-col span = exactly one head

    __nv_bfloat16* dhi = (z == 0) ? g_qhi : (z == 1) ? g_khi : g_vhi;
    __nv_bfloat16* dlo = (z == 0) ? g_qlo : (z == 1) ? g_klo : g_vlo;

    if (z == 2) {
#pragma unroll
        for (int im = 0; im < 4; im++) {
            int r = r0 + im * 16;
            int b = r >> 11, s = r & 2047;
#pragma unroll
            for (int jn = 0; jn < 8; jn++) {
                int d = (c0 + jn * 8) & 63;
                size_t off = ((size_t)(b * NUM_HEADS + hh) * SEQ + s) * D_K + d;
                uint32_t hi, lo;
                split2(acc[im][jn][0], acc[im][jn][1], hi, lo);
                *(uint32_t*)(dhi + off) = hi;
                *(uint32_t*)(dlo + off) = lo;
                split2(acc[im][jn][2], acc[im][jn][3], hi, lo);
                *(uint32_t*)(dhi + off + (size_t)8 * D_K) = hi;
                *(uint32_t*)(dlo + off + (size_t)8 * D_K) = lo;
            }
        }
    } else {
        const float scale = (z == 0) ? 0.125f : 1.0f;
        float freqf[8];
#pragma unroll
        for (int jn = 0; jn < 8; jn++) {
            int j = ((c0 + jn * 8) & 63) >> 1;
            freqf[jn] = (float)exp((double)j * -0.28782313662425575);
        }
#pragma unroll
        for (int im = 0; im < 4; im++) {
            int r = r0 + im * 16;
            int b = r >> 11, s = r & 2047;
            float p0 = (float)pos[s];
            float p1 = (float)pos[s + 8];
#pragma unroll
            for (int jn = 0; jn < 8; jn++) {
                int d = (c0 + jn * 8) & 63;
                size_t off = ((size_t)(b * NUM_HEADS + hh) * SEQ + s) * D_K + d;
                float c, sn;
                sincosf(p0 * freqf[jn], &sn, &c);
                float x1 = acc[im][jn][0], x2 = acc[im][jn][1];
                uint32_t hi, lo;
                split2((x1 * c - x2 * sn) * scale, (x1 * sn + x2 * c) * scale, hi, lo);
                *(uint32_t*)(dhi + off) = hi;
                *(uint32_t*)(dlo + off) = lo;
                sincosf(p1 * freqf[jn], &sn, &c);
                x1 = acc[im][jn][2]; x2 = acc[im][jn][3];
                split2((x1 * c - x2 * sn) * scale, (x1 * sn + x2 * c) * scale, hi, lo);
                *(uint32_t*)(dhi + off + (size_t)8 * D_K) = hi;
                *(uint32_t*)(dlo + off + (size_t)8 * D_K) = lo;
            }
        }
    }
}

// Output projection: plain fp32 epilogue.
__global__ void __launch_bounds__(256, 1) out_mma_kernel(float* __restrict__ out)
{
    extern __shared__ char smem[];
    const uint32_t sb = smem_u32(smem);
    const int bm = blockIdx.y * 128;
    const int bn = blockIdx.x * 256;
    const int tid  = threadIdx.x;
    const int wid  = tid >> 5;
    const int lane = tid & 31;
    const int wm = (wid >> 2) * 64;
    const int wn = (wid & 3) * 64;

    float acc[4][8][4];
    mma_mainloop256(g_ahi, g_alo, &g_whi[3][0], &g_wlo[3][0], acc,
                    sb, bm, bn, tid, wm, wn, lane);

    const int r0 = bm + wm + (lane >> 2);
    const int c0 = bn + wn + (lane & 3) * 2;
#pragma unroll
    for (int im = 0; im < 4; im++)
#pragma unroll
        for (int jn = 0; jn < 8; jn++) {
            float* p0 = out + (size_t)(r0 + im * 16) * D_MODEL + c0 + jn * 8;
            float* p1 = out + (size_t)(r0 + im * 16 + 8) * D_MODEL + c0 + jn * 8;
            *(float2*)p0 = make_float2(acc[im][jn][0], acc[im][jn][1]);
            *(float2*)p1 = make_float2(acc[im][jn][2], acc[im][jn][3]);
        }
}

// ---------------- Flash attention (R12-proven, unchanged) ----------------
#define KH 0
#define KL 8192
#define VH 16384
#define VL 24576
#define FLASH_SMEM 65536

__global__ void __launch_bounds__(128) flash_kernel()
{
    extern __shared__ __align__(16) char fsm[];
    const uint32_t sb = smem_u32(fsm);

    const int qt = gridDim.x - 1 - blockIdx.x;   // longest-first
    const int h  = blockIdx.y;
    const int bb = blockIdx.z;
    const int tid  = threadIdx.x;
    const int wid  = tid >> 5;
    const int lane = tid & 31;

    const size_t hoff = (size_t)(bb * NUM_HEADS + h) * SEQ * D_K;
    const __nv_bfloat16* Qh = g_qhi + hoff;
    const __nv_bfloat16* Ql = g_qlo + hoff;
    const __nv_bfloat16* Kh = g_khi + hoff;
    const __nv_bfloat16* Kl = g_klo + hoff;
    const __nv_bfloat16* Vh = g_vhi + hoff;
    const __nv_bfloat16* Vl = g_vlo + hoff;
    const int q0 = qt * 64;

    const int rA = (lane & 7) + 8 * ((lane >> 3) & 1);
    const int pA = (lane >> 4) & 1;

    for (int i = tid; i < 512; i += 128) {
        int r = i >> 3, ch = i & 7;
        int sw = r * 128 + ((ch ^ (r & 7)) << 4);
        size_t gix = (size_t)(q0 + r) * D_K + ch * 8;
        cp_async16(sb + 32768 + KH + sw, Qh + gix);
        cp_async16(sb + 32768 + KL + sw, Ql + gix);
    }
    CP_COMMIT();
    for (int i = tid; i < 512; i += 128) {
        int r = i >> 3, ch = i & 7;
        int sw = r * 128 + ((ch ^ (r & 7)) << 4);
        size_t gix = (size_t)r * D_K + ch * 8;
        cp_async16(sb + KH + sw, Kh + gix);
        cp_async16(sb + KL + sw, Kl + gix);
        cp_async16(sb + VH + sw, Vh + gix);
        cp_async16(sb + VL + sw, Vl + gix);
    }
    CP_COMMIT();

    CP_WAIT(1);
    __syncthreads();

    uint32_t aq[4][4], aql[4][4];
#pragma unroll
    for (int ks = 0; ks < 4; ks++) {
        int slot = ks * 2 + pA;
        int row  = wid * 16 + rA;
        uint32_t ad = sb + 32768 + KH + row * 128 + ((slot ^ (row & 7)) << 4);
        ldmx4(aq[ks], ad);
        ldmx4(aql[ks], ad + (KL - KH));
    }

    float out[8][4];
#pragma unroll
    for (int g = 0; g < 8; g++)
#pragma unroll
        for (int e = 0; e < 4; e++) out[g][e] = 0.f;
    float m0 = -1e30f, m1 = -1e30f, l0 = 0.f, l1 = 0.f;

    for (int kt = 0; kt <= qt; kt++) {
        const uint32_t sbs = sb + (uint32_t)(kt & 1) * 32768;
        CP_WAIT(0);
        __syncthreads();

        if (kt < qt) {
            const uint32_t sbn = sb + (uint32_t)((kt + 1) & 1) * 32768;
            for (int i = tid; i < 512; i += 128) {
                int r = i >> 3, ch = i & 7;
                int sw = r * 128 + ((ch ^ (r & 7)) << 4);
                size_t gix = (size_t)((kt + 1) * 64 + r) * D_K + ch * 8;
                cp_async16(sbn + KH + sw, Kh + gix);
                cp_async16(sbn + KL + sw, Kl + gix);
                cp_async16(sbn + VH + sw, Vh + gix);
                cp_async16(sbn + VL + sw, Vl + gix);
            }
            CP_COMMIT();
        }

        float s[8][4];
#pragma unroll
        for (int g = 0; g < 8; g++)
#pragma unroll
            for (int e = 0; e < 4; e++) s[g][e] = 0.f;

#pragma unroll
        for (int ks = 0; ks < 4; ks++) {
            const int slot = ks * 2 + pA;
            uint32_t bh[8][2], bl[8][2];
#pragma unroll
            for (int g2 = 0; g2 < 4; g2++) {
                int row = g2 * 16 + rA;
                uint32_t bd = sbs + KH + row * 128 + ((slot ^ (row & 7)) << 4);
                uint32_t t0[4], t1[4];
                ldmx4(t0, bd);
                ldmx4(t1, bd + (KL - KH));
                bh[g2 * 2 + 0][0] = t0[0]; bh[g2 * 2 + 0][1] = t0[2];
                bh[g2 * 2 + 1][0] = t0[1]; bh[g2 * 2 + 1][1] = t0[3];
                bl[g2 * 2 + 0][0] = t1[0]; bl[g2 * 2 + 0][1] = t1[2];
                bl[g2 * 2 + 1][0] = t1[1]; bl[g2 * 2 + 1][1] = t1[3];
            }
#pragma unroll
            for (int g = 0; g < 8; g++) {
                mma_bf16(s[g], aq[ks], bh[g]);
                mma_bf16(s[g], aq[ks], bl[g]);
                mma_bf16(s[g], aql[ks], bh[g]);
            }
        }

        if (kt == qt) {
            int r0 = wid * 16 + (lane >> 2);
#pragma unroll
            for (int g = 0; g < 8; g++) {
                int cb = 8 * g + 2 * (lane & 3);
                if (cb     > r0)     s[g][0] = -1e30f;
                if (cb + 1 > r0)     s[g][1] = -1e30f;
                if (cb     > r0 + 8) s[g][2] = -1e30f;
                if (cb + 1 > r0 + 8) s[g][3] = -1e30f;
            }
        }

        float mx0 = -1e30f, mx1 = -1e30f;
#pragma unroll
        for (int g = 0; g < 8; g++) {
            mx0 = fmaxf(mx0, fmaxf(s[g][0], s[g][1]));
            mx1 = fmaxf(mx1, fmaxf(s[g][2], s[g][3]));
        }
        mx0 = fmaxf(mx0, __shfl_xor_sync(0xffffffffu, mx0, 1));
        mx0 = fmaxf(mx0, __shfl_xor_sync(0xffffffffu, mx0, 2));
        mx1 = fmaxf(mx1, __shfl_xor_sync(0xffffffffu, mx1, 1));
        mx1 = fmaxf(mx1, __shfl_xor_sync(0xffffffffu, mx1, 2));

        float mn0 = fmaxf(m0, mx0), mn1 = fmaxf(m1, mx1);
        float sf0 = __expf(m0 - mn0), sf1 = __expf(m1 - mn1);
        m0 = mn0; m1 = mn1;

        float rs0 = 0.f, rs1 = 0.f;
#pragma unroll
        for (int g = 0; g < 8; g++) {
            s[g][0] = __expf(s[g][0] - mn0);
            s[g][1] = __expf(s[g][1] - mn0);
            s[g][2] = __expf(s[g][2] - mn1);
            s[g][3] = __expf(s[g][3] - mn1);
            rs0 += s[g][0] + s[g][1];
            rs1 += s[g][2] + s[g][3];
        }
        rs0 += __shfl_xor_sync(0xffffffffu, rs0, 1);
        rs0 += __shfl_xor_sync(0xffffffffu, rs0, 2);
        rs1 += __shfl_xor_sync(0xffffffffu, rs1, 1);
        rs1 += __shfl_xor_sync(0xffffffffu, rs1, 2);
        l0 = l0 * sf0 + rs0;
        l1 = l1 * sf1 + rs1;
#pragma unroll
        for (int g = 0; g < 8; g++) {
            out[g][0] *= sf0; out[g][1] *= sf0;
            out[g][2] *= sf1; out[g][3] *= sf1;
        }

        uint32_t ap[4][4], apl[4][4];
#pragma unroll
        for (int j = 0; j < 4; j++) {
            split2(s[2*j][0],   s[2*j][1],   ap[j][0], apl[j][0]);
            split2(s[2*j][2],   s[2*j][3],   ap[j][1], apl[j][1]);
            split2(s[2*j+1][0], s[2*j+1][1], ap[j][2], apl[j][2]);
            split2(s[2*j+1][2], s[2*j+1][3], ap[j][3], apl[j][3]);
        }

#pragma unroll
        for (int j = 0; j < 4; j++) {
            uint32_t bv[8][2], bvl[8][2];
            int krow = j * 16 + (lane & 7) + 8 * ((lane >> 3) & 1);
            int colh = (lane >> 4) & 1;
#pragma unroll
            for (int dp = 0; dp < 4; dp++) {
                int slot = dp * 2 + colh;
                uint32_t ad = sbs + VH + krow * 128 + ((slot ^ (krow & 7)) << 4);
                uint32_t t0[4], t1[4];
                ldmx4t(t0, ad);
                ldmx4t(t1, ad + (VL - VH));
                bv[dp * 2 + 0][0] = t0[0]; bv[dp * 2 + 0][1] = t0[1];
                bv[dp * 2 + 1][0] = t0[2]; bv[dp * 2 + 1][1] = t0[3];
                bvl[dp * 2 + 0][0] = t1[0]; bvl[dp * 2 + 0][1] = t1[1];
                bvl[dp * 2 + 1][0] = t1[2]; bvl[dp * 2 + 1][1] = t1[3];
            }
#pragma unroll
            for (int g = 0; g < 8; g++) {
                mma_bf16(out[g], ap[j], bv[g]);
                mma_bf16(out[g], ap[j], bvl[g]);
                mma_bf16(out[g], apl[j], bv[g]);
            }
        }
    }

    float inv0 = 1.f / l0, inv1 = 1.f / l1;
    int srow = q0 + wid * 16 + (lane >> 2);
    size_t base0 = ((size_t)(bb * SEQ) + srow) * D_MODEL + h * 64;
    size_t base1 = base0 + (size_t)8 * D_MODEL;
#pragma unroll
    for (int g = 0; g < 8; g++) {
        int d = 8 * g + 2 * (lane & 3);
        uint32_t hi, lo;
        split2(out[g][0] * inv0, out[g][1] * inv0, hi, lo);
        *(uint32_t*)(g_ahi + base0 + d) = hi;
        *(uint32_t*)(g_alo + base0 + d) = lo;
        split2(out[g][2] * inv1, out[g][3] * inv1, hi, lo);
        *(uint32_t*)(g_ahi + base1 + d) = hi;
        *(uint32_t*)(g_alo + base1 + d) = lo;
    }
}

// ---------------- launch ----------------
extern "C" void kernel_launch(void* const* d_in, const int* in_sizes, int n_in,
                              void* d_out, int out_size)
{
    const float* x   = (const float*)d_in[0];
    const int*   pos = (const int*)  d_in[1];
    const float* wq  = (const float*)d_in[2];
    const float* wk  = (const float*)d_in[3];
    const float* wv  = (const float*)d_in[4];
    const float* wo  = (const float*)d_in[5];
    float* out = (float*)d_out;

    (void)in_sizes; (void)n_in; (void)out_size;

    static bool attr_done = false;
    if (!attr_done) {
        cudaFuncSetAttribute(qkv_mma_kernel, cudaFuncAttributeMaxDynamicSharedMemorySize,
                             GEMM_SMEM);
        cudaFuncSetAttribute(out_mma_kernel, cudaFuncAttributeMaxDynamicSharedMemorySize,
                             GEMM_SMEM);
        cudaFuncSetAttribute(flash_kernel, cudaFuncAttributeMaxDynamicSharedMemorySize,
                             FLASH_SMEM);
        attr_done = true;
    }

    __nv_bfloat16 *xhi, *xlo;
    cudaGetSymbolAddress((void**)&xhi, g_xhi);
    cudaGetSymbolAddress((void**)&xlo, g_xlo);

    const int n4x = M_TOK * D_MODEL / 4;
    const int n4w = D_MODEL * D_MODEL / 4;

    // 0) conversions
    cvt_split_kernel<<<(n4x + 255) / 256, 256>>>((const float4*)x, xhi, xlo, n4x);
    cvt_w4_kernel<<<dim3((n4w + 255) / 256, 1, 4), 256>>>(
        (const float4*)wq, (const float4*)wk, (const float4*)wv, (const float4*)wo, n4w);

    // 1) QKV projections with fused RoPE + split epilogue (128x256 tiles)
    qkv_mma_kernel<<<dim3(D_MODEL / 256, M_TOK / 128, 3), 256, GEMM_SMEM>>>(pos);

    // 2) flash attention
    flash_kernel<<<dim3(SEQ / 64, NUM_HEADS, BATCH), 128, FLASH_SMEM>>>();

    // 3) output projection (128x256 tiles)
    out_mma_kernel<<<dim3(D_MODEL / 256, M_TOK / 128, 1), 256, GEMM_SMEM>>>(out);
}

// round 16
// speedup vs baseline: 1.1361x; 1.1361x over previous
#include <cuda_runtime.h>
#include <cuda_bf16.h>
#include <math.h>
#include <stdint.h>

#define D_MODEL   1024
#define NUM_HEADS 16
#define D_K       64
#define SEQ       2048
#define BATCH     2
#define M_TOK     (BATCH*SEQ)   // 4096

// ---------------- scratch (no allocation allowed) ----------------
__device__ __nv_bfloat16 g_xhi[(size_t)M_TOK * D_MODEL];
__device__ __nv_bfloat16 g_xlo[(size_t)M_TOK * D_MODEL];
__device__ __nv_bfloat16 g_whi[4][(size_t)D_MODEL * D_MODEL];
__device__ __nv_bfloat16 g_wlo[4][(size_t)D_MODEL * D_MODEL];
__device__ __nv_bfloat16 g_ahi[(size_t)M_TOK * D_MODEL];            // attn out hi
__device__ __nv_bfloat16 g_alo[(size_t)M_TOK * D_MODEL];            // attn out lo

#define HSZ ((size_t)BATCH * NUM_HEADS * SEQ * D_K)
__device__ __nv_bfloat16 g_qhi[HSZ], g_qlo[HSZ];
__device__ __nv_bfloat16 g_khi[HSZ], g_klo[HSZ];
__device__ __nv_bfloat16 g_vhi[HSZ], g_vlo[HSZ];

// ---------------- helpers ----------------
__device__ __forceinline__ uint32_t smem_u32(const void* p) {
    uint32_t a;
    asm("{ .reg .u64 t; cvta.to.shared.u64 t, %1; cvt.u32.u64 %0, t; }" : "=r"(a) : "l"(p));
    return a;
}

__device__ __forceinline__ void cp_async16(uint32_t dst, const void* src) {
    asm volatile("cp.async.cg.shared.global [%0], [%1], 16;" :: "r"(dst), "l"(src));
}
#define CP_COMMIT() asm volatile("cp.async.commit_group;" ::: "memory")
#define CP_WAIT(n)  asm volatile("cp.async.wait_group %0;" :: "n"(n) : "memory")

__device__ __forceinline__ void ldmx4(uint32_t* r, uint32_t addr) {
    asm volatile("ldmatrix.sync.aligned.m8n8.x4.shared.b16 {%0,%1,%2,%3}, [%4];"
                 : "=r"(r[0]), "=r"(r[1]), "=r"(r[2]), "=r"(r[3]) : "r"(addr));
}

__device__ __forceinline__ void ldmx4t(uint32_t* r, uint32_t addr) {
    asm volatile("ldmatrix.sync.aligned.m8n8.x4.trans.shared.b16 {%0,%1,%2,%3}, [%4];"
                 : "=r"(r[0]), "=r"(r[1]), "=r"(r[2]), "=r"(r[3]) : "r"(addr));
}

__device__ __forceinline__ void mma_bf16(float* d, const uint32_t* a, const uint32_t* b) {
    asm volatile("mma.sync.aligned.m16n8k16.row.col.f32.bf16.bf16.f32 "
                 "{%0,%1,%2,%3}, {%4,%5,%6,%7}, {%8,%9}, {%0,%1,%2,%3};"
                 : "+f"(d[0]), "+f"(d[1]), "+f"(d[2]), "+f"(d[3])
                 : "r"(a[0]), "r"(a[1]), "r"(a[2]), "r"(a[3]), "r"(b[0]), "r"(b[1]));
}

__device__ __forceinline__ void split2(float a, float b, uint32_t& hi, uint32_t& lo) {
    __nv_bfloat162 h = __floats2bfloat162_rn(a, b);
    float ra = a - __bfloat162float(h.x);
    float rb = b - __bfloat162float(h.y);
    __nv_bfloat162 l = __floats2bfloat162_rn(ra, rb);
    hi = *(uint32_t*)&h;
    lo = *(uint32_t*)&l;
}

// ---------------- split conversion: x + 4 weights in ONE launch (grid.z selects) ----
__global__ void cvt_all_kernel(const float4* __restrict__ x,
                               const float4* __restrict__ w0, const float4* __restrict__ w1,
                               const float4* __restrict__ w2, const float4* __restrict__ w3,
                               __nv_bfloat16* __restrict__ xhi,
                               __nv_bfloat16* __restrict__ xlo,
                               int n4w, int n4x)
{
    int i = blockIdx.x * blockDim.x + threadIdx.x;
    const int z = blockIdx.z;
    const float4* src;
    __nv_bfloat16 *dhi, *dlo;
    if (z < 4) {
        if (i >= n4w) return;
        src = (z == 0) ? w0 : (z == 1) ? w1 : (z == 2) ? w2 : w3;
        dhi = &g_whi[0][(size_t)z * D_MODEL * D_MODEL];
        dlo = &g_wlo[0][(size_t)z * D_MODEL * D_MODEL];
    } else {
        if (i >= n4x) return;
        src = x;
        dhi = xhi;
        dlo = xlo;
    }
    float4 v = src[i];
    __nv_bfloat16 h[4], l[4];
    float f[4] = {v.x, v.y, v.z, v.w};
#pragma unroll
    for (int j = 0; j < 4; j++) {
        h[j] = __float2bfloat16(f[j]);
        l[j] = __float2bfloat16(f[j] - __bfloat162float(h[j]));
    }
    *(uint2*)&dhi[(size_t)i * 4] = *(uint2*)h;
    *(uint2*)&dlo[(size_t)i * 4] = *(uint2*)l;
}

// ---------------- HMMA GEMM (R12-proven): C[M,N] = A[M,K] * W[N,K]^T ----------------
// 128x128 tile, BK=64, cp.async tile loads, single 64KB buffer, 8 warps as 2(M)x4(N).
// __launch_bounds__(256, 2): cap regs at 128 to guarantee 2 CTAs/SM.
#define GEMM_SMEM (4 * 128 * 64 * 2)

__device__ __forceinline__ void mma_mainloop(const __nv_bfloat16* __restrict__ Ahi,
                                             const __nv_bfloat16* __restrict__ Alo,
                                             const __nv_bfloat16* __restrict__ Whi,
                                             const __nv_bfloat16* __restrict__ Wlo,
                                             float acc[4][4][4],
                                             uint32_t sb, int bm, int bn,
                                             int tid, int wm, int wn, int lane)
{
    const int K = D_MODEL;
    const __nv_bfloat16* srcs[4] = {
        Ahi + (size_t)bm * K, Alo + (size_t)bm * K,
        Whi + (size_t)bn * K, Wlo + (size_t)bn * K };

#pragma unroll
    for (int i = 0; i < 4; i++)
#pragma unroll
        for (int j = 0; j < 4; j++)
#pragma unroll
            for (int e = 0; e < 4; e++) acc[i][j][e] = 0.f;

    const int rA = (lane & 7) + ((lane >> 3) & 1) * 8;
    const int pA = (lane >> 4) & 1;

    for (int c = 0; c < 16; ++c) {
        const int k0 = c * 64;
        __syncthreads();
#pragma unroll
        for (int t = 0; t < 4; t++) {
            const __nv_bfloat16* S = srcs[t];
#pragma unroll
            for (int i = tid; i < 1024; i += 256) {
                int row = i >> 3, slot = i & 7;
                cp_async16(sb + t * 16384 + row * 128 + ((slot ^ (row & 7)) << 4),
                           S + (size_t)row * K + k0 + slot * 8);
            }
        }
        CP_COMMIT();
        CP_WAIT(0);
        __syncthreads();

#pragma unroll
        for (int kk = 0; kk < 4; kk++) {
            const int slot = kk * 2 + pA;
            uint32_t ah[4][4], al[4][4], bh[4][2], bl[4][2];
#pragma unroll
            for (int im = 0; im < 4; im++) {
                int row = wm + im * 16 + rA;
                uint32_t ad = sb + row * 128 + ((slot ^ (row & 7)) << 4);
                ldmx4(ah[im], ad);
                ldmx4(al[im], ad + 16384);
            }
#pragma unroll
            for (int g = 0; g < 2; g++) {
                int row = wn + g * 16 + rA;
                uint32_t bd = sb + 32768 + row * 128 + ((slot ^ (row & 7)) << 4);
                uint32_t t0[4], t1[4];
                ldmx4(t0, bd);
                ldmx4(t1, bd + 16384);
                bh[g * 2 + 0][0] = t0[0]; bh[g * 2 + 0][1] = t0[2];
                bh[g * 2 + 1][0] = t0[1]; bh[g * 2 + 1][1] = t0[3];
                bl[g * 2 + 0][0] = t1[0]; bl[g * 2 + 0][1] = t1[2];
                bl[g * 2 + 1][0] = t1[1]; bl[g * 2 + 1][1] = t1[3];
            }
#pragma unroll
            for (int im = 0; im < 4; im++)
#pragma unroll
                for (int jn = 0; jn < 4; jn++) {
                    mma_bf16(acc[im][jn], ah[im], bh[jn]);
                    mma_bf16(acc[im][jn], ah[im], bl[jn]);
                    mma_bf16(acc[im][jn], al[im], bh[jn]);
                }
        }
    }
}

// QKV projection with fused RoPE + bf16-split epilogue (z: 0=Q,1=K,2=V).
__global__ void __launch_bounds__(256, 2) qkv_mma_kernel(const int* __restrict__ pos)
{
    extern __shared__ char smem[];
    const uint32_t sb = smem_u32(smem);
    const int z = blockIdx.z;
    const int bm = blockIdx.y * 128;
    const int bn = blockIdx.x * 128;
    const int tid  = threadIdx.x;
    const int wid  = tid >> 5;
    const int lane = tid & 31;
    const int wm = (wid >> 2) * 64;
    const int wn = (wid & 3) * 32;

    float acc[4][4][4];
    mma_mainloop(g_xhi, g_xlo, &g_whi[z][0], &g_wlo[z][0], acc,
                 sb, bm, bn, tid, wm, wn, lane);

    const int r0 = bm + wm + (lane >> 2);
    const int c0 = bn + wn + (lane & 3) * 2;

    __nv_bfloat16* dhi = (z == 0) ? g_qhi : (z == 1) ? g_khi : g_vhi;
    __nv_bfloat16* dlo = (z == 0) ? g_qlo : (z == 1) ? g_klo : g_vlo;

    if (z == 2) {
#pragma unroll
        for (int im = 0; im < 4; im++) {
            int r = r0 + im * 16;
            int b = r >> 11, s = r & 2047;     // SEQ = 2048; r,r+8 same batch
#pragma unroll
            for (int jn = 0; jn < 4; jn++) {
                int col = c0 + jn * 8;
                int h = col >> 6, d = col & 63;
                size_t off = ((size_t)(b * NUM_HEADS + h) * SEQ + s) * D_K + d;
                uint32_t hi, lo;
                split2(acc[im][jn][0], acc[im][jn][1], hi, lo);
                *(uint32_t*)(dhi + off) = hi;
                *(uint32_t*)(dlo + off) = lo;
                split2(acc[im][jn][2], acc[im][jn][3], hi, lo);
                *(uint32_t*)(dhi + off + (size_t)8 * D_K) = hi;
                *(uint32_t*)(dlo + off + (size_t)8 * D_K) = lo;
            }
        }
    } else {
        const float scale = (z == 0) ? 0.125f : 1.0f;
        float freqf[4];
#pragma unroll
        for (int jn = 0; jn < 4; jn++) {
            int j = ((c0 + jn * 8) & 63) >> 1;
            freqf[jn] = (float)exp((double)j * -0.28782313662425575);
        }
#pragma unroll
        for (int im = 0; im < 4; im++) {
            int r = r0 + im * 16;
            int b = r >> 11, s = r & 2047;
            float p0 = (float)pos[s];
            float p1 = (float)pos[s + 8];
#pragma unroll
            for (int jn = 0; jn < 4; jn++) {
                int col = c0 + jn * 8;
                int h = col >> 6, d = col & 63;
                size_t off = ((size_t)(b * NUM_HEADS + h) * SEQ + s) * D_K + d;
                float c, sn;
                sincosf(p0 * freqf[jn], &sn, &c);
                float x1 = acc[im][jn][0], x2 = acc[im][jn][1];
                uint32_t hi, lo;
                split2((x1 * c - x2 * sn) * scale, (x1 * sn + x2 * c) * scale, hi, lo);
                *(uint32_t*)(dhi + off) = hi;
                *(uint32_t*)(dlo + off) = lo;
                sincosf(p1 * freqf[jn], &sn, &c);
                x1 = acc[im][jn][2]; x2 = acc[im][jn][3];
                split2((x1 * c - x2 * sn) * scale, (x1 * sn + x2 * c) * scale, hi, lo);
                *(uint32_t*)(dhi + off + (size_t)8 * D_K) = hi;
                *(uint32_t*)(dlo + off + (size_t)8 * D_K) = lo;
            }
        }
    }
}

// Output projection: plain fp32 epilogue.
__global__ void __launch_bounds__(256, 2) out_mma_kernel(float* __restrict__ out)
{
    extern __shared__ char smem[];
    const uint32_t sb = smem_u32(smem);
    const int bm = blockIdx.y * 128;
    const int bn = blockIdx.x * 128;
    const int tid  = threadIdx.x;
    const int wid  = tid >> 5;
    const int lane = tid & 31;
    const int wm = (wid >> 2) * 64;
    const int wn = (wid & 3) * 32;

    float acc[4][4][4];
    mma_mainloop(g_ahi, g_alo, &g_whi[3][0], &g_wlo[3][0], acc,
                 sb, bm, bn, tid, wm, wn, lane);

    const int r0 = bm + wm + (lane >> 2);
    const int c0 = bn + wn + (lane & 3) * 2;
#pragma unroll
    for (int im = 0; im < 4; im++)
#pragma unroll
        for (int jn = 0; jn < 4; jn++) {
            float* p0 = out + (size_t)(r0 + im * 16) * D_MODEL + c0 + jn * 8;
            float* p1 = out + (size_t)(r0 + im * 16 + 8) * D_MODEL + c0 + jn * 8;
            *(float2*)p0 = make_float2(acc[im][jn][0], acc[im][jn][1]);
            *(float2*)p1 = make_float2(acc[im][jn][2], acc[im][jn][3]);
        }
}

// ---------------- Flash attention (R12-proven, unchanged) ----------------
#define KH 0
#define KL 8192
#define VH 16384
#define VL 24576
#define FLASH_SMEM 65536

__global__ void __launch_bounds__(128) flash_kernel()
{
    extern __shared__ __align__(16) char fsm[];
    const uint32_t sb = smem_u32(fsm);

    const int qt = gridDim.x - 1 - blockIdx.x;   // longest-first
    const int h  = blockIdx.y;
    const int bb = blockIdx.z;
    const int tid  = threadIdx.x;
    const int wid  = tid >> 5;
    const int lane = tid & 31;

    const size_t hoff = (size_t)(bb * NUM_HEADS + h) * SEQ * D_K;
    const __nv_bfloat16* Qh = g_qhi + hoff;
    const __nv_bfloat16* Ql = g_qlo + hoff;
    const __nv_bfloat16* Kh = g_khi + hoff;
    const __nv_bfloat16* Kl = g_klo + hoff;
    const __nv_bfloat16* Vh = g_vhi + hoff;
    const __nv_bfloat16* Vl = g_vlo + hoff;
    const int q0 = qt * 64;

    const int rA = (lane & 7) + 8 * ((lane >> 3) & 1);
    const int pA = (lane >> 4) & 1;

    for (int i = tid; i < 512; i += 128) {
        int r = i >> 3, ch = i & 7;
        int sw = r * 128 + ((ch ^ (r & 7)) << 4);
        size_t gix = (size_t)(q0 + r) * D_K + ch * 8;
        cp_async16(sb + 32768 + KH + sw, Qh + gix);
        cp_async16(sb + 32768 + KL + sw, Ql + gix);
    }
    CP_COMMIT();
    for (int i = tid; i < 512; i += 128) {
        int r = i >> 3, ch = i & 7;
        int sw = r * 128 + ((ch ^ (r & 7)) << 4);
        size_t gix = (size_t)r * D_K + ch * 8;
        cp_async16(sb + KH + sw, Kh + gix);
        cp_async16(sb + KL + sw, Kl + gix);
        cp_async16(sb + VH + sw, Vh + gix);
        cp_async16(sb + VL + sw, Vl + gix);
    }
    CP_COMMIT();

    CP_WAIT(1);
    __syncthreads();

    uint32_t aq[4][4], aql[4][4];
#pragma unroll
    for (int ks = 0; ks < 4; ks++) {
        int slot = ks * 2 + pA;
        int row  = wid * 16 + rA;
        uint32_t ad = sb + 32768 + KH + row * 128 + ((slot ^ (row & 7)) << 4);
        ldmx4(aq[ks], ad);
        ldmx4(aql[ks], ad + (KL - KH));
    }

    float out[8][4];
#pragma unroll
    for (int g = 0; g < 8; g++)
#pragma unroll
        for (int e = 0; e < 4; e++) out[g][e] = 0.f;
    float m0 = -1e30f, m1 = -1e30f, l0 = 0.f, l1 = 0.f;

    for (int kt = 0; kt <= qt; kt++) {
        const uint32_t sbs = sb + (uint32_t)(kt & 1) * 32768;
        CP_WAIT(0);
        __syncthreads();

        if (kt < qt) {
            const uint32_t sbn = sb + (uint32_t)((kt + 1) & 1) * 32768;
            for (int i = tid; i < 512; i += 128) {
                int r = i >> 3, ch = i & 7;
                int sw = r * 128 + ((ch ^ (r & 7)) << 4);
                size_t gix = (size_t)((kt + 1) * 64 + r) * D_K + ch * 8;
                cp_async16(sbn + KH + sw, Kh + gix);
                cp_async16(sbn + KL + sw, Kl + gix);
                cp_async16(sbn + VH + sw, Vh + gix);
                cp_async16(sbn + VL + sw, Vl + gix);
            }
            CP_COMMIT();
        }

        float s[8][4];
#pragma unroll
        for (int g = 0; g < 8; g++)
#pragma unroll
            for (int e = 0; e < 4; e++) s[g][e] = 0.f;

#pragma unroll
        for (int ks = 0; ks < 4; ks++) {
            const int slot = ks * 2 + pA;
            uint32_t bh[8][2], bl[8][2];
#pragma unroll
            for (int g2 = 0; g2 < 4; g2++) {
                int row = g2 * 16 + rA;
                uint32_t bd = sbs + KH + row * 128 + ((slot ^ (row & 7)) << 4);
                uint32_t t0[4], t1[4];
                ldmx4(t0, bd);
                ldmx4(t1, bd + (KL - KH));
                bh[g2 * 2 + 0][0] = t0[0]; bh[g2 * 2 + 0][1] = t0[2];
                bh[g2 * 2 + 1][0] = t0[1]; bh[g2 * 2 + 1][1] = t0[3];
                bl[g2 * 2 + 0][0] = t1[0]; bl[g2 * 2 + 0][1] = t1[2];
                bl[g2 * 2 + 1][0] = t1[1]; bl[g2 * 2 + 1][1] = t1[3];
            }
#pragma unroll
            for (int g = 0; g < 8; g++) {
                mma_bf16(s[g], aq[ks], bh[g]);
                mma_bf16(s[g], aq[ks], bl[g]);
                mma_bf16(s[g], aql[ks], bh[g]);
            }
        }

        if (kt == qt) {
            int r0 = wid * 16 + (lane >> 2);
#pragma unroll
            for (int g = 0; g < 8; g++) {
                int cb = 8 * g + 2 * (lane & 3);
                if (cb     > r0)     s[g][0] = -1e30f;
                if (cb + 1 > r0)     s[g][1] = -1e30f;
                if (cb     > r0 + 8) s[g][2] = -1e30f;
                if (cb + 1 > r0 + 8) s[g][3] = -1e30f;
            }
        }

        float mx0 = -1e30f, mx1 = -1e30f;
#pragma unroll
        for (int g = 0; g < 8; g++) {
            mx0 = fmaxf(mx0, fmaxf(s[g][0], s[g][1]));
            mx1 = fmaxf(mx1, fmaxf(s[g][2], s[g][3]));
        }
        mx0 = fmaxf(mx0, __shfl_xor_sync(0xffffffffu, mx0, 1));
        mx0 = fmaxf(mx0, __shfl_xor_sync(0xffffffffu, mx0, 2));
        mx1 = fmaxf(mx1, __shfl_xor_sync(0xffffffffu, mx1, 1));
        mx1 = fmaxf(mx1, __shfl_xor_sync(0xffffffffu, mx1, 2));

        float mn0 = fmaxf(m0, mx0), mn1 = fmaxf(m1, mx1);
        float sf0 = __expf(m0 - mn0), sf1 = __expf(m1 - mn1);
        m0 = mn0; m1 = mn1;

        float rs0 = 0.f, rs1 = 0.f;
#pragma unroll
        for (int g = 0; g < 8; g++) {
            s[g][0] = __expf(s[g][0] - mn0);
            s[g][1] = __expf(s[g][1] - mn0);
            s[g][2] = __expf(s[g][2] - mn1);
            s[g][3] = __expf(s[g][3] - mn1);
            rs0 += s[g][0] + s[g][1];
            rs1 += s[g][2] + s[g][3];
        }
        rs0 += __shfl_xor_sync(0xffffffffu, rs0, 1);
        rs0 += __shfl_xor_sync(0xffffffffu, rs0, 2);
        rs1 += __shfl_xor_sync(0xffffffffu, rs1, 1);
        rs1 += __shfl_xor_sync(0xffffffffu, rs1, 2);
        l0 = l0 * sf0 + rs0;
        l1 = l1 * sf1 + rs1;
#pragma unroll
        for (int g = 0; g < 8; g++) {
            out[g][0] *= sf0; out[g][1] *= sf0;
            out[g][2] *= sf1; out[g][3] *= sf1;
        }

        uint32_t ap[4][4], apl[4][4];
#pragma unroll
        for (int j = 0; j < 4; j++) {
            split2(s[2*j][0],   s[2*j][1],   ap[j][0], apl[j][0]);
            split2(s[2*j][2],   s[2*j][3],   ap[j][1], apl[j][1]);
            split2(s[2*j+1][0], s[2*j+1][1], ap[j][2], apl[j][2]);
            split2(s[2*j+1][2], s[2*j+1][3], ap[j][3], apl[j][3]);
        }

#pragma unroll
        for (int j = 0; j < 4; j++) {
            uint32_t bv[8][2], bvl[8][2];
            int krow = j * 16 + (lane & 7) + 8 * ((lane >> 3) & 1);
            int colh = (lane >> 4) & 1;
#pragma unroll
            for (int dp = 0; dp < 4; dp++) {
                int slot = dp * 2 + colh;
                uint32_t ad = sbs + VH + krow * 128 + ((slot ^ (krow & 7)) << 4);
                uint32_t t0[4], t1[4];
                ldmx4t(t0, ad);
                ldmx4t(t1, ad + (VL - VH));
                bv[dp * 2 + 0][0] = t0[0]; bv[dp * 2 + 0][1] = t0[1];
                bv[dp * 2 + 1][0] = t0[2]; bv[dp * 2 + 1][1] = t0[3];
                bvl[dp * 2 + 0][0] = t1[0]; bvl[dp * 2 + 0][1] = t1[1];
                bvl[dp * 2 + 1][0] = t1[2]; bvl[dp * 2 + 1][1] = t1[3];
            }
#pragma unroll
            for (int g = 0; g < 8; g++) {
                mma_bf16(out[g], ap[j], bv[g]);
                mma_bf16(out[g], ap[j], bvl[g]);
                mma_bf16(out[g], apl[j], bv[g]);
            }
        }
    }

    float inv0 = 1.f / l0, inv1 = 1.f / l1;
    int srow = q0 + wid * 16 + (lane >> 2);
    size_t base0 = ((size_t)(bb * SEQ) + srow) * D_MODEL + h * 64;
    size_t base1 = base0 + (size_t)8 * D_MODEL;
#pragma unroll
    for (int g = 0; g < 8; g++) {
        int d = 8 * g + 2 * (lane & 3);
        uint32_t hi, lo;
        split2(out[g][0] * inv0, out[g][1] * inv0, hi, lo);
        *(uint32_t*)(g_ahi + base0 + d) = hi;
        *(uint32_t*)(g_alo + base0 + d) = lo;
        split2(out[g][2] * inv1, out[g][3] * inv1, hi, lo);
        *(uint32_t*)(g_ahi + base1 + d) = hi;
        *(uint32_t*)(g_alo + base1 + d) = lo;
    }
}

// ---------------- launch ----------------
extern "C" void kernel_launch(void* const* d_in, const int* in_sizes, int n_in,
                              void* d_out, int out_size)
{
    const float* x   = (const float*)d_in[0];
    const int*   pos = (const int*)  d_in[1];
    const float* wq  = (const float*)d_in[2];
    const float* wk  = (const float*)d_in[3];
    const float* wv  = (const float*)d_in[4];
    const float* wo  = (const float*)d_in[5];
    float* out = (float*)d_out;

    (void)in_sizes; (void)n_in; (void)out_size;

    static bool attr_done = false;
    if (!attr_done) {
        cudaFuncSetAttribute(qkv_mma_kernel, cudaFuncAttributeMaxDynamicSharedMemorySize,
                             GEMM_SMEM);
        cudaFuncSetAttribute(out_mma_kernel, cudaFuncAttributeMaxDynamicSharedMemorySize,
                             GEMM_SMEM);
        cudaFuncSetAttribute(flash_kernel, cudaFuncAttributeMaxDynamicSharedMemorySize,
                             FLASH_SMEM);
        attr_done = true;
    }

    __nv_bfloat16 *xhi, *xlo;
    cudaGetSymbolAddress((void**)&xhi, g_xhi);
    cudaGetSymbolAddress((void**)&xlo, g_xlo);

    const int n4x = M_TOK * D_MODEL / 4;       // 1M
    const int n4w = D_MODEL * D_MODEL / 4;     // 256K

    // 0) all conversions in ONE launch (z<4: weights; z=4: x)
    cvt_all_kernel<<<dim3((n4x + 255) / 256, 1, 5), 256>>>(
        (const float4*)x, (const float4*)wq, (const float4*)wk,
        (const float4*)wv, (const float4*)wo, xhi, xlo, n4w, n4x);

    // 1) QKV projections with fused RoPE + split epilogue (R12 config, 2-CTA hint)
    qkv_mma_kernel<<<dim3(D_MODEL / 128, M_TOK / 128, 3), 256, GEMM_SMEM>>>(pos);

    // 2) flash attention
    flash_kernel<<<dim3(SEQ / 64, NUM_HEADS, BATCH), 128, FLASH_SMEM>>>();

    // 3) output projection
    out_mma_kernel<<<dim3(D_MODEL / 128, M_TOK / 128, 1), 256, GEMM_SMEM>>>(out);
}

// round 17
// speedup vs baseline: 1.1855x; 1.0436x over previous
#include <cuda_runtime.h>
#include <cuda_bf16.h>
#include <math.h>
#include <stdint.h>

#define D_MODEL   1024
#define NUM_HEADS 16
#define D_K       64
#define SEQ       2048
#define BATCH     2
#define M_TOK     (BATCH*SEQ)   // 4096

// ---------------- scratch (no allocation allowed) ----------------
__device__ __nv_bfloat16 g_xhi[(size_t)M_TOK * D_MODEL];
__device__ __nv_bfloat16 g_xlo[(size_t)M_TOK * D_MODEL];
__device__ __nv_bfloat16 g_whi[4][(size_t)D_MODEL * D_MODEL];
__device__ __nv_bfloat16 g_wlo[4][(size_t)D_MODEL * D_MODEL];
__device__ __nv_bfloat16 g_ahi[(size_t)M_TOK * D_MODEL];            // attn out hi
__device__ __nv_bfloat16 g_alo[(size_t)M_TOK * D_MODEL];            // attn out lo

#define HSZ ((size_t)BATCH * NUM_HEADS * SEQ * D_K)
__device__ __nv_bfloat16 g_qhi[HSZ], g_qlo[HSZ];
__device__ __nv_bfloat16 g_khi[HSZ], g_klo[HSZ];
__device__ __nv_bfloat16 g_vhi[HSZ], g_vlo[HSZ];

// ---------------- helpers ----------------
__device__ __forceinline__ uint32_t smem_u32(const void* p) {
    uint32_t a;
    asm("{ .reg .u64 t; cvta.to.shared.u64 t, %1; cvt.u32.u64 %0, t; }" : "=r"(a) : "l"(p));
    return a;
}

__device__ __forceinline__ void cp_async16(uint32_t dst, const void* src) {
    asm volatile("cp.async.cg.shared.global [%0], [%1], 16;" :: "r"(dst), "l"(src));
}
#define CP_COMMIT() asm volatile("cp.async.commit_group;" ::: "memory")
#define CP_WAIT(n)  asm volatile("cp.async.wait_group %0;" :: "n"(n) : "memory")

__device__ __forceinline__ void ldmx4(uint32_t* r, uint32_t addr) {
    asm volatile("ldmatrix.sync.aligned.m8n8.x4.shared.b16 {%0,%1,%2,%3}, [%4];"
                 : "=r"(r[0]), "=r"(r[1]), "=r"(r[2]), "=r"(r[3]) : "r"(addr));
}

__device__ __forceinline__ void ldmx4t(uint32_t* r, uint32_t addr) {
    asm volatile("ldmatrix.sync.aligned.m8n8.x4.trans.shared.b16 {%0,%1,%2,%3}, [%4];"
                 : "=r"(r[0]), "=r"(r[1]), "=r"(r[2]), "=r"(r[3]) : "r"(addr));
}

__device__ __forceinline__ void mma_bf16(float* d, const uint32_t* a, const uint32_t* b) {
    asm volatile("mma.sync.aligned.m16n8k16.row.col.f32.bf16.bf16.f32 "
                 "{%0,%1,%2,%3}, {%4,%5,%6,%7}, {%8,%9}, {%0,%1,%2,%3};"
                 : "+f"(d[0]), "+f"(d[1]), "+f"(d[2]), "+f"(d[3])
                 : "r"(a[0]), "r"(a[1]), "r"(a[2]), "r"(a[3]), "r"(b[0]), "r"(b[1]));
}

__device__ __forceinline__ void split2(float a, float b, uint32_t& hi, uint32_t& lo) {
    __nv_bfloat162 h = __floats2bfloat162_rn(a, b);
    float ra = a - __bfloat162float(h.x);
    float rb = b - __bfloat162float(h.y);
    __nv_bfloat162 l = __floats2bfloat162_rn(ra, rb);
    hi = *(uint32_t*)&h;
    lo = *(uint32_t*)&l;
}

// ---------------- split conversion: x + 4 weights in ONE launch (grid.z selects) ----
__global__ void cvt_all_kernel(const float4* __restrict__ x,
                               const float4* __restrict__ w0, const float4* __restrict__ w1,
                               const float4* __restrict__ w2, const float4* __restrict__ w3,
                               __nv_bfloat16* __restrict__ xhi,
                               __nv_bfloat16* __restrict__ xlo,
                               int n4w, int n4x)
{
    int i = blockIdx.x * blockDim.x + threadIdx.x;
    const int z = blockIdx.z;
    const float4* src;
    __nv_bfloat16 *dhi, *dlo;
    if (z < 4) {
        if (i >= n4w) return;
        src = (z == 0) ? w0 : (z == 1) ? w1 : (z == 2) ? w2 : w3;
        dhi = &g_whi[0][(size_t)z * D_MODEL * D_MODEL];
        dlo = &g_wlo[0][(size_t)z * D_MODEL * D_MODEL];
    } else {
        if (i >= n4x) return;
        src = x;
        dhi = xhi;
        dlo = xlo;
    }
    float4 v = src[i];
    __nv_bfloat16 h[4], l[4];
    float f[4] = {v.x, v.y, v.z, v.w};
#pragma unroll
    for (int j = 0; j < 4; j++) {
        h[j] = __float2bfloat16(f[j]);
        l[j] = __float2bfloat16(f[j] - __bfloat162float(h[j]));
    }
    *(uint2*)&dhi[(size_t)i * 4] = *(uint2*)h;
    *(uint2*)&dlo[(size_t)i * 4] = *(uint2*)l;
}

// ---------------- HMMA GEMM: 64(M)x128(N) tile, BK=64, 3 CTAs/SM -------------------
// smem: Ahi 64x64 (8KB) @0, Alo @8192, Bhi 128x64 (16KB) @16384, Blo @32768 = 48KB.
// 8 warps as 2(M)x4(N), warp tile 32x32.
#define GEMM_SMEM 49152

__device__ __forceinline__ void mma_mainloop(const __nv_bfloat16* __restrict__ Ahi,
                                             const __nv_bfloat16* __restrict__ Alo,
                                             const __nv_bfloat16* __restrict__ Whi,
                                             const __nv_bfloat16* __restrict__ Wlo,
                                             float acc[2][4][4],
                                             uint32_t sb, int bm, int bn,
                                             int tid, int wm, int wn, int lane)
{
    const int K = D_MODEL;
    const __nv_bfloat16* A0 = Ahi + (size_t)bm * K;
    const __nv_bfloat16* A1 = Alo + (size_t)bm * K;
    const __nv_bfloat16* W0 = Whi + (size_t)bn * K;
    const __nv_bfloat16* W1 = Wlo + (size_t)bn * K;

#pragma unroll
    for (int i = 0; i < 2; i++)
#pragma unroll
        for (int j = 0; j < 4; j++)
#pragma unroll
            for (int e = 0; e < 4; e++) acc[i][j][e] = 0.f;

    const int rA = (lane & 7) + ((lane >> 3) & 1) * 8;
    const int pA = (lane >> 4) & 1;

    for (int c = 0; c < 16; ++c) {
        const int k0 = c * 64;
        __syncthreads();
        // A tiles: 64 rows x 8 slots = 512 cp.async per hi/lo
#pragma unroll
        for (int i = tid; i < 512; i += 256) {
            int row = i >> 3, slot = i & 7;
            uint32_t sw = row * 128 + ((slot ^ (row & 7)) << 4);
            cp_async16(sb + sw,        A0 + (size_t)row * K + k0 + slot * 8);
            cp_async16(sb + 8192 + sw, A1 + (size_t)row * K + k0 + slot * 8);
        }
        // B tiles: 128 rows x 8 slots = 1024 per hi/lo
#pragma unroll
        for (int i = tid; i < 1024; i += 256) {
            int row = i >> 3, slot = i & 7;
            uint32_t sw = row * 128 + ((slot ^ (row & 7)) << 4);
            cp_async16(sb + 16384 + sw, W0 + (size_t)row * K + k0 + slot * 8);
            cp_async16(sb + 32768 + sw, W1 + (size_t)row * K + k0 + slot * 8);
        }
        CP_COMMIT();
        CP_WAIT(0);
        __syncthreads();

#pragma unroll
        for (int kk = 0; kk < 4; kk++) {
            const int slot = kk * 2 + pA;
            uint32_t ah[2][4], al[2][4], bh[4][2], bl[4][2];
#pragma unroll
            for (int im = 0; im < 2; im++) {
                int row = wm + im * 16 + rA;
                uint32_t ad = sb + row * 128 + ((slot ^ (row & 7)) << 4);
                ldmx4(ah[im], ad);
                ldmx4(al[im], ad + 8192);
            }
#pragma unroll
            for (int g = 0; g < 2; g++) {
                int row = wn + g * 16 + rA;
                uint32_t bd = sb + 16384 + row * 128 + ((slot ^ (row & 7)) << 4);
                uint32_t t0[4], t1[4];
                ldmx4(t0, bd);
                ldmx4(t1, bd + 16384);
                bh[g * 2 + 0][0] = t0[0]; bh[g * 2 + 0][1] = t0[2];
                bh[g * 2 + 1][0] = t0[1]; bh[g * 2 + 1][1] = t0[3];
                bl[g * 2 + 0][0] = t1[0]; bl[g * 2 + 0][1] = t1[2];
                bl[g * 2 + 1][0] = t1[1]; bl[g * 2 + 1][1] = t1[3];
            }
#pragma unroll
            for (int im = 0; im < 2; im++)
#pragma unroll
                for (int jn = 0; jn < 4; jn++) {
                    mma_bf16(acc[im][jn], ah[im], bh[jn]);
                    mma_bf16(acc[im][jn], ah[im], bl[jn]);
                    mma_bf16(acc[im][jn], al[im], bh[jn]);
                }
        }
    }
}

// QKV projection with fused RoPE + bf16-split epilogue (z: 0=Q,1=K,2=V).
__global__ void __launch_bounds__(256, 3) qkv_mma_kernel(const int* __restrict__ pos)
{
    extern __shared__ char smem[];
    const uint32_t sb = smem_u32(smem);
    const int z = blockIdx.z;
    const int bm = blockIdx.y * 64;
    const int bn = blockIdx.x * 128;
    const int tid  = threadIdx.x;
    const int wid  = tid >> 5;
    const int lane = tid & 31;
    const int wm = (wid >> 2) * 32;
    const int wn = (wid & 3) * 32;

    float acc[2][4][4];
    mma_mainloop(g_xhi, g_xlo, &g_whi[z][0], &g_wlo[z][0], acc,
                 sb, bm, bn, tid, wm, wn, lane);

    const int r0 = bm + wm + (lane >> 2);
    const int c0 = bn + wn + (lane & 3) * 2;

    __nv_bfloat16* dhi = (z == 0) ? g_qhi : (z == 1) ? g_khi : g_vhi;
    __nv_bfloat16* dlo = (z == 0) ? g_qlo : (z == 1) ? g_klo : g_vlo;

    if (z == 2) {
#pragma unroll
        for (int im = 0; im < 2; im++) {
            int r = r0 + im * 16;
            int b = r >> 11, s = r & 2047;     // SEQ = 2048; r,r+8 same batch
#pragma unroll
            for (int jn = 0; jn < 4; jn++) {
                int col = c0 + jn * 8;
                int h = col >> 6, d = col & 63;
                size_t off = ((size_t)(b * NUM_HEADS + h) * SEQ + s) * D_K + d;
                uint32_t hi, lo;
                split2(acc[im][jn][0], acc[im][jn][1], hi, lo);
                *(uint32_t*)(dhi + off) = hi;
                *(uint32_t*)(dlo + off) = lo;
                split2(acc[im][jn][2], acc[im][jn][3], hi, lo);
                *(uint32_t*)(dhi + off + (size_t)8 * D_K) = hi;
                *(uint32_t*)(dlo + off + (size_t)8 * D_K) = lo;
            }
        }
    } else {
        const float scale = (z == 0) ? 0.125f : 1.0f;
        float freqf[4];
#pragma unroll
        for (int jn = 0; jn < 4; jn++) {
            int j = ((c0 + jn * 8) & 63) >> 1;
            freqf[jn] = (float)exp((double)j * -0.28782313662425575);
        }
#pragma unroll
        for (int im = 0; im < 2; im++) {
            int r = r0 + im * 16;
            int b = r >> 11, s = r & 2047;
            float p0 = (float)pos[s];
            float p1 = (float)pos[s + 8];
#pragma unroll
            for (int jn = 0; jn < 4; jn++) {
                int col = c0 + jn * 8;
                int h = col >> 6, d = col & 63;
                size_t off = ((size_t)(b * NUM_HEADS + h) * SEQ + s) * D_K + d;
                float c, sn;
                sincosf(p0 * freqf[jn], &sn, &c);
                float x1 = acc[im][jn][0], x2 = acc[im][jn][1];
                uint32_t hi, lo;
                split2((x1 * c - x2 * sn) * scale, (x1 * sn + x2 * c) * scale, hi, lo);
                *(uint32_t*)(dhi + off) = hi;
                *(uint32_t*)(dlo + off) = lo;
                sincosf(p1 * freqf[jn], &sn, &c);
                x1 = acc[im][jn][2]; x2 = acc[im][jn][3];
                split2((x1 * c - x2 * sn) * scale, (x1 * sn + x2 * c) * scale, hi, lo);
                *(uint32_t*)(dhi + off + (size_t)8 * D_K) = hi;
                *(uint32_t*)(dlo + off + (size_t)8 * D_K) = lo;
            }
        }
    }
}

// Output projection: plain fp32 epilogue.
__global__ void __launch_bounds__(256, 3) out_mma_kernel(float* __restrict__ out)
{
    extern __shared__ char smem[];
    const uint32_t sb = smem_u32(smem);
    const int bm = blockIdx.y * 64;
    const int bn = blockIdx.x * 128;
    const int tid  = threadIdx.x;
    const int wid  = tid >> 5;
    const int lane = tid & 31;
    const int wm = (wid >> 2) * 32;
    const int wn = (wid & 3) * 32;

    float acc[2][4][4];
    mma_mainloop(g_ahi, g_alo, &g_whi[3][0], &g_wlo[3][0], acc,
                 sb, bm, bn, tid, wm, wn, lane);

    const int r0 = bm + wm + (lane >> 2);
    const int c0 = bn + wn + (lane & 3) * 2;
#pragma unroll
    for (int im = 0; im < 2; im++)
#pragma unroll
        for (int jn = 0; jn < 4; jn++) {
            float* p0 = out + (size_t)(r0 + im * 16) * D_MODEL + c0 + jn * 8;
            float* p1 = out + (size_t)(r0 + im * 16 + 8) * D_MODEL + c0 + jn * 8;
            *(float2*)p0 = make_float2(acc[im][jn][0], acc[im][jn][1]);
            *(float2*)p1 = make_float2(acc[im][jn][2], acc[im][jn][3]);
        }
}

// ---------------- Flash attention (R12-proven, unchanged) ----------------
#define KH 0
#define KL 8192
#define VH 16384
#define VL 24576
#define FLASH_SMEM 65536

__global__ void __launch_bounds__(128) flash_kernel()
{
    extern __shared__ __align__(16) char fsm[];
    const uint32_t sb = smem_u32(fsm);

    const int qt = gridDim.x - 1 - blockIdx.x;   // longest-first
    const int h  = blockIdx.y;
    const int bb = blockIdx.z;
    const int tid  = threadIdx.x;
    const int wid  = tid >> 5;
    const int lane = tid & 31;

    const size_t hoff = (size_t)(bb * NUM_HEADS + h) * SEQ * D_K;
    const __nv_bfloat16* Qh = g_qhi + hoff;
    const __nv_bfloat16* Ql = g_qlo + hoff;
    const __nv_bfloat16* Kh = g_khi + hoff;
    const __nv_bfloat16* Kl = g_klo + hoff;
    const __nv_bfloat16* Vh = g_vhi + hoff;
    const __nv_bfloat16* Vl = g_vlo + hoff;
    const int q0 = qt * 64;

    const int rA = (lane & 7) + 8 * ((lane >> 3) & 1);
    const int pA = (lane >> 4) & 1;

    for (int i = tid; i < 512; i += 128) {
        int r = i >> 3, ch = i & 7;
        int sw = r * 128 + ((ch ^ (r & 7)) << 4);
        size_t gix = (size_t)(q0 + r) * D_K + ch * 8;
        cp_async16(sb + 32768 + KH + sw, Qh + gix);
        cp_async16(sb + 32768 + KL + sw, Ql + gix);
    }
    CP_COMMIT();
    for (int i = tid; i < 512; i += 128) {
        int r = i >> 3, ch = i & 7;
        int sw = r * 128 + ((ch ^ (r & 7)) << 4);
        size_t gix = (size_t)r * D_K + ch * 8;
        cp_async16(sb + KH + sw, Kh + gix);
        cp_async16(sb + KL + sw, Kl + gix);
        cp_async16(sb + VH + sw, Vh + gix);
        cp_async16(sb + VL + sw, Vl + gix);
    }
    CP_COMMIT();

    CP_WAIT(1);
    __syncthreads();

    uint32_t aq[4][4], aql[4][4];
#pragma unroll
    for (int ks = 0; ks < 4; ks++) {
        int slot = ks * 2 + pA;
        int row  = wid * 16 + rA;
        uint32_t ad = sb + 32768 + KH + row * 128 + ((slot ^ (row & 7)) << 4);
        ldmx4(aq[ks], ad);
        ldmx4(aql[ks], ad + (KL - KH));
    }

    float out[8][4];
#pragma unroll
    for (int g = 0; g < 8; g++)
#pragma unroll
        for (int e = 0; e < 4; e++) out[g][e] = 0.f;
    float m0 = -1e30f, m1 = -1e30f, l0 = 0.f, l1 = 0.f;

    for (int kt = 0; kt <= qt; kt++) {
        const uint32_t sbs = sb + (uint32_t)(kt & 1) * 32768;
        CP_WAIT(0);
        __syncthreads();

        if (kt < qt) {
            const uint32_t sbn = sb + (uint32_t)((kt + 1) & 1) * 32768;
            for (int i = tid; i < 512; i += 128) {
                int r = i >> 3, ch = i & 7;
                int sw = r * 128 + ((ch ^ (r & 7)) << 4);
                size_t gix = (size_t)((kt + 1) * 64 + r) * D_K + ch * 8;
                cp_async16(sbn + KH + sw, Kh + gix);
                cp_async16(sbn + KL + sw, Kl + gix);
                cp_async16(sbn + VH + sw, Vh + gix);
                cp_async16(sbn + VL + sw, Vl + gix);
            }
            CP_COMMIT();
        }

        float s[8][4];
#pragma unroll
        for (int g = 0; g < 8; g++)
#pragma unroll
            for (int e = 0; e < 4; e++) s[g][e] = 0.f;

#pragma unroll
        for (int ks = 0; ks < 4; ks++) {
            const int slot = ks * 2 + pA;
            uint32_t bh[8][2], bl[8][2];
#pragma unroll
            for (int g2 = 0; g2 < 4; g2++) {
                int row = g2 * 16 + rA;
                uint32_t bd = sbs + KH + row * 128 + ((slot ^ (row & 7)) << 4);
                uint32_t t0[4], t1[4];
                ldmx4(t0, bd);
                ldmx4(t1, bd + (KL - KH));
                bh[g2 * 2 + 0][0] = t0[0]; bh[g2 * 2 + 0][1] = t0[2];
                bh[g2 * 2 + 1][0] = t0[1]; bh[g2 * 2 + 1][1] = t0[3];
                bl[g2 * 2 + 0][0] = t1[0]; bl[g2 * 2 + 0][1] = t1[2];
                bl[g2 * 2 + 1][0] = t1[1]; bl[g2 * 2 + 1][1] = t1[3];
            }
#pragma unroll
            for (int g = 0; g < 8; g++) {
                mma_bf16(s[g], aq[ks], bh[g]);
                mma_bf16(s[g], aq[ks], bl[g]);
                mma_bf16(s[g], aql[ks], bh[g]);
            }
        }

        if (kt == qt) {
            int r0 = wid * 16 + (lane >> 2);
#pragma unroll
            for (int g = 0; g < 8; g++) {
                int cb = 8 * g + 2 * (lane & 3);
                if (cb     > r0)     s[g][0] = -1e30f;
                if (cb + 1 > r0)     s[g][1] = -1e30f;
                if (cb     > r0 + 8) s[g][2] = -1e30f;
                if (cb + 1 > r0 + 8) s[g][3] = -1e30f;
            }
        }

        float mx0 = -1e30f, mx1 = -1e30f;
#pragma unroll
        for (int g = 0; g < 8; g++) {
            mx0 = fmaxf(mx0, fmaxf(s[g][0], s[g][1]));
            mx1 = fmaxf(mx1, fmaxf(s[g][2], s[g][3]));
        }
        mx0 = fmaxf(mx0, __shfl_xor_sync(0xffffffffu, mx0, 1));
        mx0 = fmaxf(mx0, __shfl_xor_sync(0xffffffffu, mx0, 2));
        mx1 = fmaxf(mx1, __shfl_xor_sync(0xffffffffu, mx1, 1));
        mx1 = fmaxf(mx1, __shfl_xor_sync(0xffffffffu, mx1, 2));

        float mn0 = fmaxf(m0, mx0), mn1 = fmaxf(m1, mx1);
        float sf0 = __expf(m0 - mn0), sf1 = __expf(m1 - mn1);
        m0 = mn0; m1 = mn1;

        float rs0 = 0.f, rs1 = 0.f;
#pragma unroll
        for (int g = 0; g < 8; g++) {
            s[g][0] = __expf(s[g][0] - mn0);
            s[g][1] = __expf(s[g][1] - mn0);
            s[g][2] = __expf(s[g][2] - mn1);
            s[g][3] = __expf(s[g][3] - mn1);
            rs0 += s[g][0] + s[g][1];
            rs1 += s[g][2] + s[g][3];
        }
        rs0 += __shfl_xor_sync(0xffffffffu, rs0, 1);
        rs0 += __shfl_xor_sync(0xffffffffu, rs0, 2);
        rs1 += __shfl_xor_sync(0xffffffffu, rs1, 1);
        rs1 += __shfl_xor_sync(0xffffffffu, rs1, 2);
        l0 = l0 * sf0 + rs0;
        l1 = l1 * sf1 + rs1;
#pragma unroll
        for (int g = 0; g < 8; g++) {
            out[g][0] *= sf0; out[g][1] *= sf0;
            out[g][2] *= sf1; out[g][3] *= sf1;
        }

        uint32_t ap[4][4], apl[4][4];
#pragma unroll
        for (int j = 0; j < 4; j++) {
            split2(s[2*j][0],   s[2*j][1],   ap[j][0], apl[j][0]);
            split2(s[2*j][2],   s[2*j][3],   ap[j][1], apl[j][1]);
            split2(s[2*j+1][0], s[2*j+1][1], ap[j][2], apl[j][2]);
            split2(s[2*j+1][2], s[2*j+1][3], ap[j][3], apl[j][3]);
        }

#pragma unroll
        for (int j = 0; j < 4; j++) {
            uint32_t bv[8][2], bvl[8][2];
            int krow = j * 16 + (lane & 7) + 8 * ((lane >> 3) & 1);
            int colh = (lane >> 4) & 1;
#pragma unroll
            for (int dp = 0; dp < 4; dp++) {
                int slot = dp * 2 + colh;
                uint32_t ad = sbs + VH + krow * 128 + ((slot ^ (krow & 7)) << 4);
                uint32_t t0[4], t1[4];
                ldmx4t(t0, ad);
                ldmx4t(t1, ad + (VL - VH));
                bv[dp * 2 + 0][0] = t0[0]; bv[dp * 2 + 0][1] = t0[1];
                bv[dp * 2 + 1][0] = t0[2]; bv[dp * 2 + 1][1] = t0[3];
                bvl[dp * 2 + 0][0] = t1[0]; bvl[dp * 2 + 0][1] = t1[1];
                bvl[dp * 2 + 1][0] = t1[2]; bvl[dp * 2 + 1][1] = t1[3];
            }
#pragma unroll
            for (int g = 0; g < 8; g++) {
                mma_bf16(out[g], ap[j], bv[g]);
                mma_bf16(out[g], ap[j], bvl[g]);
                mma_bf16(out[g], apl[j], bv[g]);
            }
        }
    }

    float inv0 = 1.f / l0, inv1 = 1.f / l1;
    int srow = q0 + wid * 16 + (lane >> 2);
    size_t base0 = ((size_t)(bb * SEQ) + srow) * D_MODEL + h * 64;
    size_t base1 = base0 + (size_t)8 * D_MODEL;
#pragma unroll
    for (int g = 0; g < 8; g++) {
        int d = 8 * g + 2 * (lane & 3);
        uint32_t hi, lo;
        split2(out[g][0] * inv0, out[g][1] * inv0, hi, lo);
        *(uint32_t*)(g_ahi + base0 + d) = hi;
        *(uint32_t*)(g_alo + base0 + d) = lo;
        split2(out[g][2] * inv1, out[g][3] * inv1, hi, lo);
        *(uint32_t*)(g_ahi + base1 + d) = hi;
        *(uint32_t*)(g_alo + base1 + d) = lo;
    }
}

// ---------------- launch ----------------
extern "C" void kernel_launch(void* const* d_in, const int* in_sizes, int n_in,
                              void* d_out, int out_size)
{
    const float* x   = (const float*)d_in[0];
    const int*   pos = (const int*)  d_in[1];
    const float* wq  = (const float*)d_in[2];
    const float* wk  = (const float*)d_in[3];
    const float* wv  = (const float*)d_in[4];
    const float* wo  = (const float*)d_in[5];
    float* out = (float*)d_out;

    (void)in_sizes; (void)n_in; (void)out_size;

    static bool attr_done = false;
    if (!attr_done) {
        cudaFuncSetAttribute(qkv_mma_kernel, cudaFuncAttributeMaxDynamicSharedMemorySize,
                             GEMM_SMEM);
        cudaFuncSetAttribute(out_mma_kernel, cudaFuncAttributeMaxDynamicSharedMemorySize,
                             GEMM_SMEM);
        cudaFuncSetAttribute(flash_kernel, cudaFuncAttributeMaxDynamicSharedMemorySize,
                             FLASH_SMEM);
        attr_done = true;
    }

    __nv_bfloat16 *xhi, *xlo;
    cudaGetSymbolAddress((void**)&xhi, g_xhi);
    cudaGetSymbolAddress((void**)&xlo, g_xlo);

    const int n4x = M_TOK * D_MODEL / 4;       // 1M
    const int n4w = D_MODEL * D_MODEL / 4;     // 256K

    // 0) all conversions in ONE launch (z<4: weights; z=4: x)
    cvt_all_kernel<<<dim3((n4x + 255) / 256, 1, 5), 256>>>(
        (const float4*)x, (const float4*)wq, (const float4*)wk,
        (const float4*)wv, (const float4*)wo, xhi, xlo, n4w, n4x);

    // 1) QKV projections with fused RoPE + split epilogue (64x128 tiles, 3 CTAs/SM)
    qkv_mma_kernel<<<dim3(D_MODEL / 128, M_TOK / 64, 3), 256, GEMM_SMEM>>>(pos);

    // 2) flash attention
    flash_kernel<<<dim3(SEQ / 64, NUM_HEADS, BATCH), 128, FLASH_SMEM>>>();

    // 3) output projection (64x128 tiles)
    out_mma_kernel<<<dim3(D_MODEL / 128, M_TOK / 64, 1), 256, GEMM_SMEM>>>(out);
}